// round 4
// baseline (speedup 1.0000x reference)
#include <cuda_runtime.h>
#include <cuda_bf16.h>

#define BETA   0.001f
#define TPB    256
#define NBLK   296
#define MAXSEG 8192
#define LOG2E  1.4426950408889634f
#define LN2    0.6931471805599453f

__device__ float    g_seg[MAXSEG];
__device__ unsigned g_next = 0;
__device__ unsigned g_done = 0;

__device__ __forceinline__ float ex2f(float x){ float r; asm("ex2.approx.f32 %0,%1;":"=f"(r):"f"(x)); return r; }
__device__ __forceinline__ float lg2f(float x){ float r; asm("lg2.approx.f32 %0,%1;":"=f"(r):"f"(x)); return r; }

// Dense sweep: i-chunk at b[0..31] against NJ j-chunks with exps e[0..NJ-1].
// Chain j accumulates prod(1 + e[j]*b[i]); lg2 taken every 8 factors (pa:even, pb:odd)
// to stay in fp32 range (factor <= ~2^14, 4 factors/chain-half -> <= 2^56, product <= 2^112).
// Chain j==0 is the DIAGONAL chunk (rj==ri): weight 1/2 (symmetrization identity).
template<int NJ>
__device__ __forceinline__ void sweep(const float* __restrict__ b,
                                      const float* __restrict__ e,
                                      float& acc)
{
    #pragma unroll
    for (int blk = 0; blk < 4; ++blk) {
        float pa[NJ], pb[NJ];
        #pragma unroll
        for (int j = 0; j < NJ; ++j) { pa[j] = 1.0f; pb[j] = 1.0f; }
        #pragma unroll
        for (int k = 0; k < 8; k += 2) {
            float b0 = b[blk * 8 + k];
            float b1 = b[blk * 8 + k + 1];
            #pragma unroll
            for (int j = 0; j < NJ; ++j) {
                float t0 = e[j] * b0; pa[j] = fmaf(pa[j], t0, pa[j]);
                float t1 = e[j] * b1; pb[j] = fmaf(pb[j], t1, pb[j]);
            }
        }
        #pragma unroll
        for (int j = 0; j < NJ; ++j) {
            float w = (j == 0) ? 0.5f : 1.0f;
            acc += w * lg2f(pa[j] * pb[j]);
        }
    }
}

__global__ void __launch_bounds__(TPB) rm_kernel(
    const float* __restrict__ logits,
    const void*  __restrict__ cu_raw,
    int n_seg,
    float* __restrict__ out)
{
    __shared__ float em[TPB / 32][128];
    __shared__ float ws[TPB / 32];
    __shared__ bool  isLast;

    const int tid  = threadIdx.x;
    const int w    = tid >> 5;
    const int lane = tid & 31;

    const int*       cu32 = (const int*)cu_raw;
    const long long* cu64 = (const long long*)cu_raw;
    const bool is64 = (cu32[1] == 0);   // cu[0]=0 -> word[1]==0 only in int64 layout

    // First fetch
    int s = -1;
    if (lane == 0) s = (int)atomicAdd(&g_next, 1u);
    s = __shfl_sync(0xffffffffu, s, 0);
    long long a = 0, bnd = 0;
    if (s < n_seg) {
        if (is64) { a = cu64[s]; bnd = cu64[s + 1]; }
        else      { a = (long long)cu32[s]; bnd = (long long)cu32[s + 1]; }
    }

    while (s < n_seg) {
        const int L = (int)(bnd - a);
        const int C = (L + 31) >> 5;
        const float* gx = logits + a;

        // Issue x loads early
        float x[4];
        #pragma unroll
        for (int r = 0; r < 4; ++r) {
            int j = (r << 5) + lane;
            x[r] = (j < L) ? gx[j] : 0.0f;
        }

        // Prefetch next segment (cu latency hides under the sweeps)
        int s2 = -1;
        if (lane == 0) s2 = (int)atomicAdd(&g_next, 1u);
        s2 = __shfl_sync(0xffffffffu, s2, 0);
        long long a2 = 0, b2 = 0;
        if (s2 < n_seg) {
            if (is64) { a2 = cu64[s2]; b2 = cu64[s2 + 1]; }
            else      { a2 = (long long)cu32[s2]; b2 = (long long)cu32[s2 + 1]; }
        }

        // Per-element precompute: E+ = 2^{x log2e} (regs), E- = 2^{-x log2e} (shared, 0-padded),
        // sq = sum x^2, wsum = sum over diag-chunk-local i<j of (x_j - x_i) linear weights.
        float ej[4];
        float sq = 0.0f, wsum = 0.0f;
        #pragma unroll
        for (int r = 0; r < 4; ++r) {
            int j = (r << 5) + lane;
            bool v = (j < L);
            float xv = x[r];
            sq += xv * xv;
            int nv = L - (r << 5); nv = (nv > 32) ? 32 : nv;   // valid elems in chunk r
            if (v) wsum += xv * (float)(2 * lane - (nv - 1));
            float xl = xv * LOG2E;
            ej[r]    = v ? ex2f(xl)  : 0.0f;
            em[w][j] = v ? ex2f(-xl) : 0.0f;
        }
        __syncwarp();

        // acc = sum_{cross chunk pairs} log2(1+e^z)  +  0.5 * sum_{diag chunks} F_full
        float acc = 0.0f;
        const float* base = em[w];
        switch (C) {
            case 1:  sweep<1>(base,      ej,     acc); break;
            case 2:  sweep<2>(base,      ej,     acc);
                     sweep<1>(base + 32, ej + 1, acc); break;
            case 3:  sweep<3>(base,      ej,     acc);
                     sweep<2>(base + 32, ej + 1, acc);
                     sweep<1>(base + 64, ej + 2, acc); break;
            default: sweep<4>(base,      ej,     acc);
                     sweep<3>(base + 32, ej + 1, acc);
                     sweep<2>(base + 64, ej + 2, acc);
                     sweep<1>(base + 96, ej + 3, acc); break;
        }
        __syncwarp();

        #pragma unroll
        for (int o = 16; o > 0; o >>= 1) {
            acc  += __shfl_xor_sync(0xffffffffu, acc,  o);
            sq   += __shfl_xor_sync(0xffffffffu, sq,   o);
            wsum += __shfl_xor_sync(0xffffffffu, wsum, o);
        }
        if (lane == 0) {
            // tri = ln2*acc + 0.5*wsum - 0.5*ln2*L   (diag symmetrization correction)
            float pair_nats = fmaf(LN2, acc, fmaf(0.5f, wsum, -0.34657359027997264f * (float)L));
            float invP = 2.0f / ((float)L * (float)(L - 1));
            g_seg[s] = pair_nats * invP + sq * (BETA / (float)L);
        }

        s = s2; a = a2; bnd = b2;
    }

    __syncthreads();
    if (tid == 0) {
        __threadfence();
        unsigned v = atomicAdd(&g_done, 1u);
        isLast = (v == gridDim.x - 1);
    }
    __syncthreads();

    if (isLast) {
        float v = 0.0f;
        for (int k = tid; k < n_seg; k += TPB) v += g_seg[k];   // fixed order: deterministic
        #pragma unroll
        for (int o = 16; o > 0; o >>= 1) v += __shfl_xor_sync(0xffffffffu, v, o);
        if (lane == 0) ws[w] = v;
        __syncthreads();
        if (w == 0) {
            v = (lane < TPB / 32) ? ws[lane] : 0.0f;
            #pragma unroll
            for (int o = 4; o > 0; o >>= 1) v += __shfl_xor_sync(0xffffffffu, v, o);
            if (lane == 0) {
                out[0] = v / (float)n_seg;
                g_next = 0;     // reset for next graph replay
                g_done = 0;
            }
        }
    }
}

extern "C" void kernel_launch(void* const* d_in, const int* in_sizes, int n_in,
                              void* d_out, int out_size) {
    const float* logits = (const float*)d_in[0];
    const void*  cu     = (const void*)d_in[1];
    int n_seg = in_sizes[1] - 1;
    if (n_seg > MAXSEG) n_seg = MAXSEG;

    rm_kernel<<<NBLK, TPB>>>(logits, cu, n_seg, (float*)d_out);
}

// round 5
// speedup vs baseline: 1.2353x; 1.2353x over previous
#include <cuda_runtime.h>
#include <cuda_bf16.h>

#define BETA   0.001f
#define TPB    256
#define WPB    8
#define MAXB   1024
#define LOG2E  1.4426950408889634f
#define LN2    0.6931471805599453f

__device__ float    g_part[MAXB];
__device__ unsigned g_done = 0;

__device__ __forceinline__ float ex2f(float x){ float r; asm("ex2.approx.f32 %0,%1;":"=f"(r):"f"(x)); return r; }
__device__ __forceinline__ float lg2f(float x){ float r; asm("lg2.approx.f32 %0,%1;":"=f"(r):"f"(x)); return r; }

// Dense sweep: i-chunk b[0..31] vs NJ j-chunks with exps e[0..NJ-1].
// Chain j accumulates prod(1 + e[j]*b[i]); lg2 every 8 factors (pa: even i, pb: odd i).
// Factor <= ~2^14, 4 factors/half-chain -> pa,pb <= 2^56, pa*pb <= 2^112 (no overflow).
// Chain j==0 is the DIAGONAL chunk (rj==ri): weight 1/2 (symmetrization identity).
template<int NJ>
__device__ __forceinline__ void sweep(const float* __restrict__ b,
                                      const float* __restrict__ e,
                                      float& acc)
{
    #pragma unroll
    for (int blk = 0; blk < 4; ++blk) {
        float pa[NJ], pb[NJ];
        #pragma unroll
        for (int j = 0; j < NJ; ++j) { pa[j] = 1.0f; pb[j] = 1.0f; }
        #pragma unroll
        for (int k = 0; k < 8; k += 2) {
            float b0 = b[blk * 8 + k];
            float b1 = b[blk * 8 + k + 1];
            #pragma unroll
            for (int j = 0; j < NJ; ++j) {
                float t0 = e[j] * b0; pa[j] = fmaf(pa[j], t0, pa[j]);
                float t1 = e[j] * b1; pb[j] = fmaf(pb[j], t1, pb[j]);
            }
        }
        #pragma unroll
        for (int j = 0; j < NJ; ++j) {
            float w = (j == 0) ? 0.5f : 1.0f;
            acc += w * lg2f(pa[j] * pb[j]);
        }
    }
}

__global__ void __launch_bounds__(TPB) rm_kernel(
    const float* __restrict__ logits,
    const void*  __restrict__ cu_raw,
    int n_seg,
    float* __restrict__ out)
{
    __shared__ float em[WPB][128];
    __shared__ float part[WPB];
    __shared__ float ws[TPB / 32];
    __shared__ bool  isLast;

    const int tid  = threadIdx.x;
    const int w    = tid >> 5;
    const int lane = tid & 31;
    const int s    = blockIdx.x * WPB + w;

    float per_seg = 0.0f;

    if (s < n_seg) {
        const int* cu32 = (const int*)cu_raw;
        long long a, bnd;
        if (cu32[1] == 0) {                 // int64 layout (cu[0]=0)
            const long long* cu64 = (const long long*)cu_raw;
            a = cu64[s]; bnd = cu64[s + 1];
        } else {
            a = (long long)cu32[s]; bnd = (long long)cu32[s + 1];
        }
        const int L = (int)(bnd - a);
        const int C = (L + 31) >> 5;
        const float* gx = logits + a;

        // Per-element precompute:
        //   E+_j = 2^{x log2e} (regs), E-_i = 2^{-x log2e} (shared, zero-padded),
        //   sq   = sum x^2,
        //   wsum = sum x_k * (2 k_local - (nv-1))   (= 2 * sum_{i<j local} (x_j - x_i) per diag chunk)
        float ej[4];
        float sq = 0.0f, wsum = 0.0f;
        #pragma unroll
        for (int r = 0; r < 4; ++r) {
            int j = (r << 5) + lane;
            bool v = (j < L);
            float xv = v ? gx[j] : 0.0f;
            sq += xv * xv;
            int nv = L - (r << 5); nv = (nv > 32) ? 32 : nv;
            if (v) wsum += xv * (float)(2 * lane - (nv - 1));
            float xl = xv * LOG2E;
            ej[r]    = v ? ex2f(xl)  : 0.0f;
            em[w][j] = v ? ex2f(-xl) : 0.0f;
        }
        __syncwarp();

        // acc = sum_{cross chunk pairs} log2(1+e^z) + 0.5 * sum_{diag chunks} F_full(log2)
        float acc = 0.0f;
        const float* base = em[w];
        switch (C) {
            case 1:  sweep<1>(base,      ej,     acc); break;
            case 2:  sweep<2>(base,      ej,     acc);
                     sweep<1>(base + 32, ej + 1, acc); break;
            case 3:  sweep<3>(base,      ej,     acc);
                     sweep<2>(base + 32, ej + 1, acc);
                     sweep<1>(base + 64, ej + 2, acc); break;
            default: sweep<4>(base,      ej,     acc);
                     sweep<3>(base + 32, ej + 1, acc);
                     sweep<2>(base + 64, ej + 2, acc);
                     sweep<1>(base + 96, ej + 3, acc); break;
        }

        // Fold per-segment uniform coefficients in BEFORE reduction -> one value.
        // tri_nats = ln2*acc + 0.5*wsum - 0.5*ln2*L ;  per_seg = tri_nats*invP + sq*BETA/L
        float invP = 2.0f / ((float)L * (float)(L - 1));
        float v = acc  * (LN2 * invP)
                + wsum * (0.5f * invP)
                + sq   * (BETA / (float)L);
        #pragma unroll
        for (int o = 16; o > 0; o >>= 1)
            v += __shfl_xor_sync(0xffffffffu, v, o);
        per_seg = v - 0.5f * LN2 * (float)L * invP;   // constant diag correction
    }

    if (lane == 0) part[w] = per_seg;
    __syncthreads();

    if (tid == 0) {
        float p = 0.0f;
        #pragma unroll
        for (int k = 0; k < WPB; ++k) p += part[k];
        g_part[blockIdx.x] = p;
        __threadfence();
        unsigned d = atomicAdd(&g_done, 1u);
        isLast = (d == gridDim.x - 1);
    }
    __syncthreads();

    if (isLast) {
        float v = 0.0f;
        for (int k = tid; k < (int)gridDim.x; k += TPB) v += g_part[k];  // fixed order
        #pragma unroll
        for (int o = 16; o > 0; o >>= 1) v += __shfl_xor_sync(0xffffffffu, v, o);
        if (lane == 0) ws[w] = v;
        __syncthreads();
        if (w == 0) {
            v = (lane < TPB / 32) ? ws[lane] : 0.0f;
            #pragma unroll
            for (int o = 4; o > 0; o >>= 1) v += __shfl_xor_sync(0xffffffffu, v, o);
            if (lane == 0) {
                out[0] = v / (float)n_seg;
                g_done = 0;   // reset for next graph replay
            }
        }
    }
}

extern "C" void kernel_launch(void* const* d_in, const int* in_sizes, int n_in,
                              void* d_out, int out_size) {
    const float* logits = (const float*)d_in[0];
    const void*  cu     = (const void*)d_in[1];
    int n_seg  = in_sizes[1] - 1;
    int blocks = (n_seg + WPB - 1) / WPB;
    if (blocks > MAXB) blocks = MAXB;

    rm_kernel<<<blocks, TPB>>>(logits, cu, n_seg, (float*)d_out);
}

// round 6
// speedup vs baseline: 1.2663x; 1.0251x over previous
#include <cuda_runtime.h>
#include <cuda_bf16.h>

#define BETA   0.001f
#define TPB    256
#define SPB    4        // segments per block (2 warps each)
#define MAXB   2048
#define LOG2E  1.4426950408889634f
#define LN2    0.6931471805599453f

__device__ float    g_part[MAXB];
__device__ unsigned g_done = 0;

__device__ __forceinline__ float ex2f(float x){ float r; asm("ex2.approx.f32 %0,%1;":"=f"(r):"f"(x)); return r; }
__device__ __forceinline__ float lg2f(float x){ float r; asm("lg2.approx.f32 %0,%1;":"=f"(r):"f"(x)); return r; }

// One 32x32 dense chunk-block: lane j vs 32 i's from shared (zero-padded).
// prod(1 + e*b_i), lg2 every 8 factors (pa: even, pb: odd). Factor <= ~2^14,
// 4 per half-chain -> pa*pb <= 2^112, no overflow. e==0 (invalid j) -> result 0.
__device__ __forceinline__ float sweep1(const float* __restrict__ b, float e) {
    float acc = 0.0f;
    #pragma unroll
    for (int blk = 0; blk < 4; ++blk) {
        float4 v0 = *(const float4*)(b + blk * 8);
        float4 v1 = *(const float4*)(b + blk * 8 + 4);
        float pa = fmaf(e, v0.x, 1.0f);
        float pb = fmaf(e, v0.y, 1.0f);
        float t;
        t = e * v0.z; pa = fmaf(pa, t, pa);
        t = e * v0.w; pb = fmaf(pb, t, pb);
        t = e * v1.x; pa = fmaf(pa, t, pa);
        t = e * v1.y; pb = fmaf(pb, t, pb);
        t = e * v1.z; pa = fmaf(pa, t, pa);
        t = e * v1.w; pb = fmaf(pb, t, pb);
        acc += lg2f(pa * pb);
    }
    return acc;
}

__global__ void __launch_bounds__(TPB) rm_kernel(
    const float* __restrict__ logits,
    const void*  __restrict__ cu_raw,
    int n_seg,
    float* __restrict__ out)
{
    __shared__ __align__(16) float em[SPB][128];   // e^{-x}, zero-padded
    __shared__ __align__(16) float ep[SPB][128];   // e^{+x}, zero-padded
    __shared__ float partv[SPB][2];
    __shared__ float ws[TPB / 32];
    __shared__ bool  isLast;

    const int tid  = threadIdx.x;
    const int w    = tid >> 5;
    const int lane = tid & 31;
    const int segl = w >> 1;        // segment slot in block
    const int sub  = w & 1;         // which half-warp-pair member
    const int s    = blockIdx.x * SPB + segl;
    const bool segv = (s < n_seg);

    int L = 2, C = 0;
    const float* gx = logits;
    if (segv) {
        const int* cu32 = (const int*)cu_raw;
        long long a, bnd;
        if (cu32[1] == 0) {                     // int64 layout (cu[0]=0)
            const long long* cu64 = (const long long*)cu_raw;
            a = cu64[s]; bnd = cu64[s + 1];
        } else {
            a = (long long)cu32[s]; bnd = (long long)cu32[s + 1];
        }
        L = (int)(bnd - a);
        C = (L + 31) >> 5;
        gx = logits + a;
    }

    // Stage: warp `sub` covers chunks {2*sub, 2*sub+1}. Partial sq / wsum per warp
    // (linear in x -> partials combine after uniform-coefficient folding).
    float sq = 0.0f, wsum = 0.0f;
    if (segv) {
        #pragma unroll
        for (int rr = 0; rr < 2; ++rr) {
            int r = sub * 2 + rr;
            int j = (r << 5) + lane;
            bool valid = (j < L);
            float xv = valid ? gx[j] : 0.0f;
            sq += xv * xv;
            int nv = L - (r << 5); nv = (nv > 32) ? 32 : nv;
            if (valid) wsum += xv * (float)(2 * lane - (nv - 1));
            float xl = xv * LOG2E;
            ep[segl][j] = valid ? ex2f(xl)  : 0.0f;
            em[segl][j] = valid ? ex2f(-xl) : 0.0f;
        }
    }
    __syncthreads();

    // Sweep: chunk-pairs (ri <= rj < C) assigned by parity to the two warps.
    // Diagonal (ri==rj) uses symmetrization: weight 1/2 + linear correction (wsum).
    float acc = 0.0f, accd = 0.0f;
    if (segv) {
        const float* base = em[segl];
        int p = 0;
        for (int rj = 0; rj < C; ++rj) {
            float e = ep[segl][(rj << 5) + lane];
            for (int ri = 0; ri <= rj; ++ri) {
                if ((p & 1) == sub) {
                    float r = sweep1(base + (ri << 5), e);
                    if (ri == rj) accd += r; else acc += r;
                }
                ++p;
            }
        }
    }

    // Fold per-segment uniform coefficients before the warp reduction.
    // tri_nats = LN2*(acc + 0.5*accd) + 0.5*wsum - 0.5*LN2*L ; per_seg = tri*invP + sq*BETA/L
    float v = 0.0f;
    if (segv) {
        float invP = 2.0f / ((float)L * (float)(L - 1));
        v = (acc + 0.5f * accd) * (LN2 * invP)
          + wsum * (0.5f * invP)
          + sq   * (BETA / (float)L);
    }
    #pragma unroll
    for (int o = 16; o > 0; o >>= 1)
        v += __shfl_xor_sync(0xffffffffu, v, o);
    if (lane == 0) {
        if (segv && sub == 0) v -= LN2 / (float)(L - 1);   // constant diag term, once
        partv[segl][sub] = v;
    }
    __syncthreads();

    if (tid == 0) {
        float p = 0.0f;
        #pragma unroll
        for (int k = 0; k < SPB; ++k) p += partv[k][0] + partv[k][1];
        g_part[blockIdx.x] = p;
        __threadfence();
        unsigned d = atomicAdd(&g_done, 1u);
        isLast = (d == gridDim.x - 1);
    }
    __syncthreads();

    if (isLast) {
        float t = 0.0f;
        for (int k = tid; k < (int)gridDim.x; k += TPB) t += g_part[k];  // fixed order
        #pragma unroll
        for (int o = 16; o > 0; o >>= 1) t += __shfl_xor_sync(0xffffffffu, t, o);
        if (lane == 0) ws[w] = t;
        __syncthreads();
        if (w == 0) {
            t = (lane < TPB / 32) ? ws[lane] : 0.0f;
            #pragma unroll
            for (int o = 4; o > 0; o >>= 1) t += __shfl_xor_sync(0xffffffffu, t, o);
            if (lane == 0) {
                out[0] = t / (float)n_seg;
                g_done = 0;   // reset for next graph replay
            }
        }
    }
}

extern "C" void kernel_launch(void* const* d_in, const int* in_sizes, int n_in,
                              void* d_out, int out_size) {
    const float* logits = (const float*)d_in[0];
    const void*  cu     = (const void*)d_in[1];
    int n_seg  = in_sizes[1] - 1;
    int blocks = (n_seg + SPB - 1) / SPB;
    if (blocks > MAXB) blocks = MAXB;

    rm_kernel<<<blocks, TPB>>>(logits, cu, n_seg, (float*)d_out);
}